// round 13
// baseline (speedup 1.0000x reference)
#include <cuda_runtime.h>
#include <cuda_fp16.h>
#include <cstdint>
#include <math.h>

#define D_MODEL 2048
#define NHEADS  16
#define DHEAD   128
#define BATCH   64
#define TLEN    128
#define NROWS   (BATCH * TLEN)   // 8192

typedef __half f16;
typedef uint32_t u32;

// ---------------- fp16 plane scratch ----------------
__device__ f16 g_xhi[(size_t)NROWS * D_MODEL];
__device__ f16 g_qhi[(size_t)NROWS * D_MODEL];
__device__ f16 g_qlo[(size_t)NROWS * D_MODEL];
__device__ f16 g_khi[(size_t)NROWS * D_MODEL];
__device__ f16 g_vhi[(size_t)NROWS * D_MODEL];
__device__ f16 g_ahi[(size_t)NROWS * D_MODEL];
__device__ f16 g_wqh[(size_t)D_MODEL * D_MODEL];
__device__ f16 g_wkh[(size_t)D_MODEL * D_MODEL];
__device__ f16 g_wvh[(size_t)D_MODEL * D_MODEL];
__device__ f16 g_woh[(size_t)D_MODEL * D_MODEL];
__device__ float g_cos[TLEN * 64];
__device__ float g_sin[TLEN * 64];

// ---------------- primitives ----------------
__device__ __forceinline__ void mma16816(float* c, const u32* a, const u32* b) {
    asm volatile(
        "mma.sync.aligned.m16n8k16.row.col.f32.f16.f16.f32 "
        "{%0,%1,%2,%3}, {%4,%5,%6,%7}, {%8,%9}, {%0,%1,%2,%3};"
        : "+f"(c[0]), "+f"(c[1]), "+f"(c[2]), "+f"(c[3])
        : "r"(a[0]), "r"(a[1]), "r"(a[2]), "r"(a[3]), "r"(b[0]), "r"(b[1]));
}
__device__ __forceinline__ void ldmx4(u32* r, u32 addr) {
    asm volatile("ldmatrix.sync.aligned.m8n8.x4.shared.b16 {%0,%1,%2,%3}, [%4];"
                 : "=r"(r[0]), "=r"(r[1]), "=r"(r[2]), "=r"(r[3]) : "r"(addr));
}
__device__ __forceinline__ void ldmx4t(u32* r, u32 addr) {
    asm volatile("ldmatrix.sync.aligned.m8n8.x4.trans.shared.b16 {%0,%1,%2,%3}, [%4];"
                 : "=r"(r[0]), "=r"(r[1]), "=r"(r[2]), "=r"(r[3]) : "r"(addr));
}
__device__ __forceinline__ u32 smem_u32(const void* p) {
    return (u32)__cvta_generic_to_shared(p);
}
#define CP_ASYNC16(dst, src) \
    asm volatile("cp.async.cg.shared.global [%0], [%1], 16;" :: "r"(dst), "l"(src))
#define CP_COMMIT() asm volatile("cp.async.commit_group;" ::: "memory")
#define CP_WAIT(n)  asm volatile("cp.async.wait_group %0;" :: "n"(n) : "memory")

__device__ __forceinline__ u32 pack_h2(f16 a, f16 b) {
    __half2 h; h.x = a; h.y = b;
    return *(u32*)&h;
}
__device__ __forceinline__ void split2h(float e, float o, u32& hi, u32& lo) {
    f16 eh = __float2half_rn(e);
    f16 oh = __float2half_rn(o);
    float er = e - __half2float(eh);
    float orr = o - __half2float(oh);
    hi = pack_h2(eh, oh);
    lo = pack_h2(__float2half_rn(er), __float2half_rn(orr));
}
__device__ __forceinline__ u32 pack1h(float e, float o) {
    return pack_h2(__float2half_rn(e), __float2half_rn(o));
}

// ---------------- fused round-to-fp16 + RoPE table ----------------
#define NX4 (NROWS * D_MODEL / 4)
#define NW4 (D_MODEL * D_MODEL / 4)
__global__ void split_all(const float* __restrict__ x,  const float* __restrict__ wq,
                          const float* __restrict__ wk, const float* __restrict__ wv,
                          const float* __restrict__ wo,
                          f16* xhi, f16* wqh, f16* wkh, f16* wvh, f16* woh) {
    int i = blockIdx.x * blockDim.x + threadIdx.x;
    if (i < TLEN * 64) {
        int t = i >> 6;
        int k = i & 63;
        double theta = exp(-(double)k * (9.210340371976184 / 64.0));
        double ang = (double)t * theta;
        g_cos[i] = (float)cos(ang);
        g_sin[i] = (float)sin(ang);
    }
    const float* src;
    f16* hi;
    int j;
    if (i < NX4) {
        src = x; hi = xhi; j = i;
    } else {
        int r = i - NX4;
        int region = r / NW4;
        j = r - region * NW4;
        switch (region) {
            case 0:  src = wq; hi = wqh; break;
            case 1:  src = wk; hi = wkh; break;
            case 2:  src = wv; hi = wvh; break;
            default: src = wo; hi = woh; break;
        }
    }
    float4 v = ((const float4*)src)[j];
    uint2 H;
    H.x = pack1h(v.x, v.y);
    H.y = pack1h(v.z, v.w);
    ((uint2*)hi)[j] = H;
}

// ---------------- GEMM mainloop: CTA 128x128, 8 warps (2x4), warp tile 64x32 ----------
// Single-pass fp16: C = A*B. SMEM planes: A, B (80B rows), 5 stages, prefetch dist 4.
#define PLANE_B     (128 * 80)                 // 10240
#define NSTAGE      5
#define GEMM_SMEM_1 (NSTAGE * 2 * PLANE_B)     // 102400

struct AccT { float a[4][4][4]; };

__device__ __forceinline__ void gemm_mainloop(
    const f16* __restrict__ Ah, const f16* __restrict__ Bh,
    size_t arow0, size_t brow0, int K, AccT& A) {
    constexpr u32 STAGEB = 2 * PLANE_B;
    extern __shared__ char smem[];
    const u32 sb = smem_u32(smem);
    const int tid  = threadIdx.x;
    const int wid  = tid >> 5;
    const int lane = tid & 31;
    const int warp_m = (wid >> 2) * 64;   // 0 or 64
    const int warp_n = (wid & 3) * 32;    // 0,32,64,96

    const u32 a_off = (u32)(warp_m + (lane & 15)) * 80u + ((lane >> 4) * 16u);
    const u32 b_off = (u32)(warp_n + (lane & 7) + ((lane >> 4) & 1) * 8) * 80u +
                      ((lane >> 3) & 1) * 16u;

#pragma unroll
    for (int i = 0; i < 4; i++)
#pragma unroll
        for (int j = 0; j < 4; j++)
#pragma unroll
            for (int q = 0; q < 4; q++) A.a[i][j][q] = 0.0f;

    const int NCHUNK = K >> 5;  // 64
    const f16* planes[2] = {Ah, Bh};

    // 1024 16B-chunks per stage, 256 threads -> 4 per thread
    auto issue_stage = [&](int s, int ki) {
        const int kofs = ki * 32;
#pragma unroll
        for (int i = 0; i < 4; i++) {
            const int c = i * 256 + tid;
            const int pl = c >> 9;
            const int cc = c & 511;
            const int row = cc >> 2;
            const int ch = cc & 3;
            const size_t grow = (pl == 0 ? arow0 : brow0) + row;
            const f16* src = planes[pl] + grow * K + kofs + ch * 8;
            const u32 dst = sb + s * STAGEB + pl * PLANE_B + row * 80 + ch * 16;
            CP_ASYNC16(dst, src);
        }
    };

    issue_stage(0, 0); CP_COMMIT();
    issue_stage(1, 1); CP_COMMIT();
    issue_stage(2, 2); CP_COMMIT();
    issue_stage(3, 3); CP_COMMIT();

    int sidx = 0;
    for (int ki = 0; ki < NCHUNK; ki++) {
        CP_WAIT(3);
        __syncthreads();
        const u32 stage = sb + (u32)sidx * STAGEB;

#pragma unroll
        for (int ks = 0; ks < 2; ks++) {
            const u32 kbyte = (u32)ks * 32u;
            u32 ah[4][4], bh[4][2];
#pragma unroll
            for (int mt = 0; mt < 4; mt++)
                ldmx4(ah[mt], stage + a_off + (u32)mt * (16u * 80u) + kbyte);
#pragma unroll
            for (int np = 0; np < 2; np++) {
                u32 t[4];
                ldmx4(t, stage + PLANE_B + b_off + (u32)np * (16u * 80u) + kbyte);
                bh[2 * np][0] = t[0]; bh[2 * np][1] = t[1];
                bh[2 * np + 1][0] = t[2]; bh[2 * np + 1][1] = t[3];
            }
#pragma unroll
            for (int mt = 0; mt < 4; mt++)
#pragma unroll
                for (int nt = 0; nt < 4; nt++)
                    mma16816(A.a[mt][nt], ah[mt], bh[nt]);
        }
        if (ki + 4 < NCHUNK) {
            int ns = sidx + 4; if (ns >= NSTAGE) ns -= NSTAGE;
            issue_stage(ns, ki + 4);
        }
        CP_COMMIT();
        if (++sidx >= NSTAGE) sidx = 0;
    }
}

// ---------------- fused QKV GEMM, single-pass fp16 (gridDim.z = 3) ----------------
__global__ void __launch_bounds__(256, 2)
gemm_qkv(const f16* __restrict__ Xhi,
         const f16* __restrict__ WQh, const f16* __restrict__ WKh,
         const f16* __restrict__ WVh,
         f16* __restrict__ Qh, f16* __restrict__ Ql,
         f16* __restrict__ Kh, f16* __restrict__ Vh) {
    const int z = blockIdx.z;
    const f16* Bh;
    f16 *Chi, *Clo;
    if (z == 0)      { Bh = WQh; Chi = Qh; Clo = Ql; }
    else if (z == 1) { Bh = WKh; Chi = Kh; Clo = nullptr; }
    else             { Bh = WVh; Chi = Vh; Clo = nullptr; }
    const bool rope = (z < 2);

    AccT A;
    gemm_mainloop(Xhi, Bh,
                  (size_t)blockIdx.y * 128, (size_t)blockIdx.x * 128, D_MODEL, A);

    const int tid  = threadIdx.x;
    const int wid  = tid >> 5;
    const int lane = tid & 31;
    const int warp_m = (wid >> 2) * 64;
    const int warp_n = (wid & 3) * 32;
    const int rbase = blockIdx.y * 128 + warp_m + (lane >> 2);
    const int cbase = blockIdx.x * 128 + warp_n + (lane & 3) * 2;
#pragma unroll
    for (int mt = 0; mt < 4; mt++) {
#pragma unroll
        for (int half = 0; half < 2; half++) {
            const int grow = rbase + mt * 16 + half * 8;
            const int t = grow & (TLEN - 1);
#pragma unroll
            for (int nt = 0; nt < 4; nt++) {
                const int gcol = cbase + nt * 8;
                float e = A.a[mt][nt][half * 2 + 0];
                float o = A.a[mt][nt][half * 2 + 1];
                if (rope) {
                    const int kidx = (gcol & 127) >> 1;
                    const float cs = g_cos[t * 64 + kidx];
                    const float sn = g_sin[t * 64 + kidx];
                    const float e2 = e * cs - o * sn;
                    o = e * sn + o * cs;
                    e = e2;
                }
                const size_t idx = ((size_t)grow * D_MODEL + gcol) >> 1;
                if (Clo) {
                    u32 hi, lo;
                    split2h(e, o, hi, lo);
                    ((u32*)Chi)[idx] = hi;
                    ((u32*)Clo)[idx] = lo;
                } else {
                    ((u32*)Chi)[idx] = pack1h(e, o);
                }
            }
        }
    }
}

// ---------------- output GEMM, single-pass (fp32 out) ----------------
__global__ void __launch_bounds__(256, 2)
gemm_out(const f16* __restrict__ Ah, const f16* __restrict__ Bh,
         float* __restrict__ Cf) {
    AccT A;
    gemm_mainloop(Ah, Bh,
                  (size_t)blockIdx.y * 128, (size_t)blockIdx.x * 128, D_MODEL, A);

    const int tid  = threadIdx.x;
    const int wid  = tid >> 5;
    const int lane = tid & 31;
    const int warp_m = (wid >> 2) * 64;
    const int warp_n = (wid & 3) * 32;
    const int rbase = blockIdx.y * 128 + warp_m + (lane >> 2);
    const int cbase = blockIdx.x * 128 + warp_n + (lane & 3) * 2;
#pragma unroll
    for (int mt = 0; mt < 4; mt++)
#pragma unroll
        for (int half = 0; half < 2; half++) {
            const int grow = rbase + mt * 16 + half * 8;
#pragma unroll
            for (int nt = 0; nt < 4; nt++) {
                const int gcol = cbase + nt * 8;
                float2 v;
                v.x = A.a[mt][nt][half * 2 + 0];
                v.y = A.a[mt][nt][half * 2 + 1];
                *(float2*)(Cf + (size_t)grow * D_MODEL + gcol) = v;
            }
        }
}

// ---------------- attention: one CTA per (b,h), staged K/V waits ----------------
#define AT_PLANE  (128 * 272)
#define ATT_SMEM  (2 * AT_PLANE)       // Kh + Vh

__global__ void __launch_bounds__(256, 1)
attn_mma(const f16* __restrict__ Qhi, const f16* __restrict__ Qlo,
         const f16* __restrict__ Khi, const f16* __restrict__ Vhi,
         f16* __restrict__ Ahi) {
    extern __shared__ char smem[];
    const u32 sb = smem_u32(smem);
    const u32 skh = sb;
    const u32 svh = sb + AT_PLANE;

    const int bh_ = blockIdx.x;
    const int b = bh_ >> 4;
    const int h = bh_ & 15;
    const int tid = threadIdx.x;
    const int w = tid >> 5;
    const int l = tid & 31;

    // K plane first (own commit group), then V plane
    {
#pragma unroll
        for (int i = 0; i < 8; i++) {
            const int c = i * 256 + tid;
            const int row = c >> 4;
            const int ch = c & 15;
            const f16* src = Khi + ((size_t)(b * 128 + row)) * D_MODEL + h * 128 + ch * 8;
            CP_ASYNC16(skh + row * 272 + ch * 16, src);
        }
        CP_COMMIT();
#pragma unroll
        for (int i = 0; i < 8; i++) {
            const int c = i * 256 + tid;
            const int row = c >> 4;
            const int ch = c & 15;
            const f16* src = Vhi + ((size_t)(b * 128 + row)) * D_MODEL + h * 128 + ch * 8;
            CP_ASYNC16(svh + row * 272 + ch * 16, src);
        }
        CP_COMMIT();
    }

    u32 aQh[8][4], aQl[8][4];
    {
        const u32* qh32 = (const u32*)Qhi;
        const u32* ql32 = (const u32*)Qlo;
        const size_t r0 = (size_t)(b * 128 + 16 * w + (l >> 2)) * (D_MODEL / 2) + h * 64 + (l & 3);
        const size_t r8 = r0 + 8 * (D_MODEL / 2);
#pragma unroll
        for (int kt = 0; kt < 8; kt++) {
            const size_t o = (size_t)kt * 8;
            aQh[kt][0] = qh32[r0 + o];     aQh[kt][1] = qh32[r8 + o];
            aQh[kt][2] = qh32[r0 + o + 4]; aQh[kt][3] = qh32[r8 + o + 4];
            aQl[kt][0] = ql32[r0 + o];     aQl[kt][1] = ql32[r8 + o];
            aQl[kt][2] = ql32[r0 + o + 4]; aQl[kt][3] = ql32[r8 + o + 4];
        }
    }
    CP_WAIT(1);          // K resident; V still in flight
    __syncthreads();

    float S[16][4];
#pragma unroll
    for (int nt = 0; nt < 16; nt++)
#pragma unroll
        for (int q = 0; q < 4; q++) S[nt][q] = 0.0f;

    const u32 kb_off = (u32)((l & 7) + 8 * ((l >> 4) & 1)) * 272u + ((l >> 3) & 1) * 16u;
#pragma unroll
    for (int np = 0; np < 8; np++) {
        if (np <= w) {
#pragma unroll
            for (int kt = 0; kt < 8; kt++) {
                u32 kh[4];
                const u32 ro = (u32)np * (16u * 272u) + (u32)kt * 32u;
                ldmx4(kh, skh + kb_off + ro);
                u32 bh0[2] = {kh[0], kh[1]}, bh1[2] = {kh[2], kh[3]};
                mma16816(S[2 * np],     aQh[kt], bh0);
                mma16816(S[2 * np + 1], aQh[kt], bh1);
                mma16816(S[2 * np],     aQl[kt], bh0);
                mma16816(S[2 * np + 1], aQl[kt], bh1);
            }
        }
    }

    const int q0 = 16 * w + (l >> 2);
    const int q1 = q0 + 8;
    const float scale = 0.08838834764831845f;
    float m0 = -1.0e30f, m1 = -1.0e30f;
#pragma unroll
    for (int nt = 0; nt < 16; nt++) {
        if (nt <= 2 * w + 1) {
            const int kc = nt * 8 + 2 * (l & 3);
            if (kc > q0)     S[nt][0] = -1.0e30f;
            if (kc + 1 > q0) S[nt][1] = -1.0e30f;
            if (kc > q1)     S[nt][2] = -1.0e30f;
            if (kc + 1 > q1) S[nt][3] = -1.0e30f;
            m0 = fmaxf(m0, fmaxf(S[nt][0], S[nt][1]));
            m1 = fmaxf(m1, fmaxf(S[nt][2], S[nt][3]));
        }
    }
    m0 = fmaxf(m0, __shfl_xor_sync(0xffffffffu, m0, 1));
    m0 = fmaxf(m0, __shfl_xor_sync(0xffffffffu, m0, 2));
    m1 = fmaxf(m1, __shfl_xor_sync(0xffffffffu, m1, 1));
    m1 = fmaxf(m1, __shfl_xor_sync(0xffffffffu, m1, 2));

    float sum0 = 0.0f, sum1 = 0.0f;
#pragma unroll
    for (int nt = 0; nt < 16; nt++) {
        if (nt <= 2 * w + 1) {
            S[nt][0] = __expf((S[nt][0] - m0) * scale);
            S[nt][1] = __expf((S[nt][1] - m0) * scale);
            S[nt][2] = __expf((S[nt][2] - m1) * scale);
            S[nt][3] = __expf((S[nt][3] - m1) * scale);
            sum0 += S[nt][0] + S[nt][1];
            sum1 += S[nt][2] + S[nt][3];
        }
    }
    sum0 += __shfl_xor_sync(0xffffffffu, sum0, 1);
    sum0 += __shfl_xor_sync(0xffffffffu, sum0, 2);
    sum1 += __shfl_xor_sync(0xffffffffu, sum1, 1);
    sum1 += __shfl_xor_sync(0xffffffffu, sum1, 2);
    const float inv0 = 1.0f / sum0;
    const float inv1 = 1.0f / sum1;

    u32 ph[8][4], pl[8][4];
#pragma unroll
    for (int j = 0; j < 8; j++) {
        if (j <= w) {
            split2h(S[2 * j][0],     S[2 * j][1],     ph[j][0], pl[j][0]);
            split2h(S[2 * j][2],     S[2 * j][3],     ph[j][1], pl[j][1]);
            split2h(S[2 * j + 1][0], S[2 * j + 1][1], ph[j][2], pl[j][2]);
            split2h(S[2 * j + 1][2], S[2 * j + 1][3], ph[j][3], pl[j][3]);
        }
    }

    CP_WAIT(0);          // V resident
    __syncthreads();

    float O[16][4];
#pragma unroll
    for (int nt = 0; nt < 16; nt++)
#pragma unroll
        for (int q = 0; q < 4; q++) O[nt][q] = 0.0f;

    const u32 vb_row = (u32)((l & 7) + 8 * ((l >> 3) & 1)) * 272u + ((l >> 4) & 1) * 16u;
#pragma unroll
    for (int j = 0; j < 8; j++) {
        if (j <= w) {
#pragma unroll
            for (int dp = 0; dp < 8; dp += 2) {
                u32 vh0[4], vh1[4];
                const u32 ro0 = (u32)j * (16u * 272u) + (u32)dp * 32u;
                const u32 ro1 = ro0 + 32u;
                ldmx4t(vh0, svh + vb_row + ro0);
                ldmx4t(vh1, svh + vb_row + ro1);
                u32 h00[2] = {vh0[0], vh0[1]}, h01[2] = {vh0[2], vh0[3]};
                u32 h10[2] = {vh1[0], vh1[1]}, h11[2] = {vh1[2], vh1[3]};
                float* O0 = O[2 * dp];
                float* O1 = O[2 * dp + 1];
                float* O2 = O[2 * dp + 2];
                float* O3 = O[2 * dp + 3];
                mma16816(O0, ph[j], h00); mma16816(O1, ph[j], h01);
                mma16816(O2, ph[j], h10); mma16816(O3, ph[j], h11);
                mma16816(O0, pl[j], h00); mma16816(O1, pl[j], h01);
                mma16816(O2, pl[j], h10); mma16816(O3, pl[j], h11);
            }
        }
    }

    {
        u32* ah32 = (u32*)Ahi;
        const size_t rA = (size_t)(b * 128 + q0) * (D_MODEL / 2) + h * 64 + (l & 3);
        const size_t rB = rA + 8 * (D_MODEL / 2);
#pragma unroll
        for (int nt = 0; nt < 16; nt++) {
            ah32[rA + nt * 4] = pack1h(O[nt][0] * inv0, O[nt][1] * inv0);
            ah32[rB + nt * 4] = pack1h(O[nt][2] * inv1, O[nt][3] * inv1);
        }
    }
}

// ---------------- launch ----------------
extern "C" void kernel_launch(void* const* d_in, const int* in_sizes, int n_in,
                              void* d_out, int out_size) {
    const float* x  = (const float*)d_in[0];
    const float* WQ = (const float*)d_in[1];
    const float* WK = (const float*)d_in[2];
    const float* WV = (const float*)d_in[3];
    const float* WO = (const float*)d_in[4];
    float* out = (float*)d_out;

    static f16 *xhi, *qhi, *qlo, *khi, *vhi, *ahi;
    static f16 *wqh, *wkh, *wvh, *woh;
    static bool inited = false;
    if (!inited) {
        cudaGetSymbolAddress((void**)&xhi, g_xhi);
        cudaGetSymbolAddress((void**)&qhi, g_qhi); cudaGetSymbolAddress((void**)&qlo, g_qlo);
        cudaGetSymbolAddress((void**)&khi, g_khi); cudaGetSymbolAddress((void**)&vhi, g_vhi);
        cudaGetSymbolAddress((void**)&ahi, g_ahi);
        cudaGetSymbolAddress((void**)&wqh, g_wqh); cudaGetSymbolAddress((void**)&wkh, g_wkh);
        cudaGetSymbolAddress((void**)&wvh, g_wvh); cudaGetSymbolAddress((void**)&woh, g_woh);
        cudaFuncSetAttribute(gemm_qkv, cudaFuncAttributeMaxDynamicSharedMemorySize, GEMM_SMEM_1);
        cudaFuncSetAttribute(gemm_out, cudaFuncAttributeMaxDynamicSharedMemorySize, GEMM_SMEM_1);
        cudaFuncSetAttribute(attn_mma, cudaFuncAttributeMaxDynamicSharedMemorySize, ATT_SMEM);
        inited = true;
    }

    const int ntot = NX4 + 4 * NW4;
    split_all<<<(ntot + 255) / 256, 256>>>(x, WQ, WK, WV, WO,
                                           xhi, wqh, wkh, wvh, woh);

    dim3 gq(D_MODEL / 128, NROWS / 128, 3);   // (16, 64, 3)
    dim3 blk(256);
    gemm_qkv<<<gq, blk, GEMM_SMEM_1>>>(xhi, wqh, wkh, wvh, qhi, qlo, khi, vhi);

    attn_mma<<<BATCH * NHEADS, 256, ATT_SMEM>>>(qhi, qlo, khi, vhi, ahi);

    dim3 go(D_MODEL / 128, NROWS / 128);      // (16, 64)
    gemm_out<<<go, blk, GEMM_SMEM_1>>>(ahi, woh, out);
}

// round 15
// speedup vs baseline: 1.1154x; 1.1154x over previous
#include <cuda_runtime.h>
#include <cuda_fp16.h>
#include <cstdint>
#include <math.h>

#define D_MODEL 2048
#define NHEADS  16
#define DHEAD   128
#define BATCH   64
#define TLEN    128
#define NROWS   (BATCH * TLEN)   // 8192

typedef __half f16;
typedef uint32_t u32;

// ---------------- fp16 plane scratch ----------------
__device__ f16 g_xhi[(size_t)NROWS * D_MODEL];
__device__ f16 g_qhi[(size_t)NROWS * D_MODEL];
__device__ f16 g_qlo[(size_t)NROWS * D_MODEL];
__device__ f16 g_khi[(size_t)NROWS * D_MODEL];
__device__ f16 g_vhi[(size_t)NROWS * D_MODEL];
__device__ f16 g_ahi[(size_t)NROWS * D_MODEL];
__device__ f16 g_wqh[(size_t)D_MODEL * D_MODEL];
__device__ f16 g_wkh[(size_t)D_MODEL * D_MODEL];
__device__ f16 g_wvh[(size_t)D_MODEL * D_MODEL];
__device__ f16 g_woh[(size_t)D_MODEL * D_MODEL];
__device__ float g_cos[TLEN * 64];
__device__ float g_sin[TLEN * 64];

// ---------------- primitives ----------------
__device__ __forceinline__ void mma16816(float* c, const u32* a, const u32* b) {
    asm volatile(
        "mma.sync.aligned.m16n8k16.row.col.f32.f16.f16.f32 "
        "{%0,%1,%2,%3}, {%4,%5,%6,%7}, {%8,%9}, {%0,%1,%2,%3};"
        : "+f"(c[0]), "+f"(c[1]), "+f"(c[2]), "+f"(c[3])
        : "r"(a[0]), "r"(a[1]), "r"(a[2]), "r"(a[3]), "r"(b[0]), "r"(b[1]));
}
__device__ __forceinline__ void ldmx4(u32* r, u32 addr) {
    asm volatile("ldmatrix.sync.aligned.m8n8.x4.shared.b16 {%0,%1,%2,%3}, [%4];"
                 : "=r"(r[0]), "=r"(r[1]), "=r"(r[2]), "=r"(r[3]) : "r"(addr));
}
__device__ __forceinline__ void ldmx4t(u32* r, u32 addr) {
    asm volatile("ldmatrix.sync.aligned.m8n8.x4.trans.shared.b16 {%0,%1,%2,%3}, [%4];"
                 : "=r"(r[0]), "=r"(r[1]), "=r"(r[2]), "=r"(r[3]) : "r"(addr));
}
__device__ __forceinline__ u32 smem_u32(const void* p) {
    return (u32)__cvta_generic_to_shared(p);
}
#define CP_ASYNC16(dst, src) \
    asm volatile("cp.async.cg.shared.global [%0], [%1], 16;" :: "r"(dst), "l"(src))
#define CP_COMMIT() asm volatile("cp.async.commit_group;" ::: "memory")
#define CP_WAIT(n)  asm volatile("cp.async.wait_group %0;" :: "n"(n) : "memory")

__device__ __forceinline__ u32 pack_h2(f16 a, f16 b) {
    __half2 h; h.x = a; h.y = b;
    return *(u32*)&h;
}
__device__ __forceinline__ void split2h(float e, float o, u32& hi, u32& lo) {
    f16 eh = __float2half_rn(e);
    f16 oh = __float2half_rn(o);
    float er = e - __half2float(eh);
    float orr = o - __half2float(oh);
    hi = pack_h2(eh, oh);
    lo = pack_h2(__float2half_rn(er), __float2half_rn(orr));
}
__device__ __forceinline__ u32 pack1h(float e, float o) {
    return pack_h2(__float2half_rn(e), __float2half_rn(o));
}

// ---------------- fused round-to-fp16 + RoPE table ----------------
#define NX4 (NROWS * D_MODEL / 4)
#define NW4 (D_MODEL * D_MODEL / 4)
__global__ void split_all(const float* __restrict__ x,  const float* __restrict__ wq,
                          const float* __restrict__ wk, const float* __restrict__ wv,
                          const float* __restrict__ wo,
                          f16* xhi, f16* wqh, f16* wkh, f16* wvh, f16* woh) {
    int i = blockIdx.x * blockDim.x + threadIdx.x;
    if (i < TLEN * 64) {
        int t = i >> 6;
        int k = i & 63;
        double theta = exp(-(double)k * (9.210340371976184 / 64.0));
        double ang = (double)t * theta;
        g_cos[i] = (float)cos(ang);
        g_sin[i] = (float)sin(ang);
    }
    const float* src;
    f16* hi;
    int j;
    if (i < NX4) {
        src = x; hi = xhi; j = i;
    } else {
        int r = i - NX4;
        int region = r / NW4;
        j = r - region * NW4;
        switch (region) {
            case 0:  src = wq; hi = wqh; break;
            case 1:  src = wk; hi = wkh; break;
            case 2:  src = wv; hi = wvh; break;
            default: src = wo; hi = woh; break;
        }
    }
    float4 v = ((const float4*)src)[j];
    uint2 H;
    H.x = pack1h(v.x, v.y);
    H.y = pack1h(v.z, v.w);
    ((uint2*)hi)[j] = H;
}

// ---------------- GEMM mainloop: CTA 128x128, 8 warps (2x4), warp tile 64x32 ----------
// Single-pass fp16, BK=64. SMEM rows 128B data + 16B pad = 144B stride.
// 3 stages x 36KB = 108KB -> 2 CTAs/SM. 32 barrier windows, 64 MMAs each.
#define RSTRIDE     144
#define PLANE_B     (128 * RSTRIDE)            // 18432
#define NSTAGE      3
#define STAGE_B     (2 * PLANE_B)              // 36864
#define GEMM_SMEM_1 (NSTAGE * STAGE_B)         // 110592

struct AccT { float a[4][4][4]; };

__device__ __forceinline__ void gemm_mainloop(
    const f16* __restrict__ Ah, const f16* __restrict__ Bh,
    size_t arow0, size_t brow0, int K, AccT& A) {
    extern __shared__ char smem[];
    const u32 sb = smem_u32(smem);
    const int tid  = threadIdx.x;
    const int wid  = tid >> 5;
    const int lane = tid & 31;
    const int warp_m = (wid >> 2) * 64;   // 0 or 64
    const int warp_n = (wid & 3) * 32;    // 0,32,64,96

    const u32 a_off = (u32)(warp_m + (lane & 15)) * RSTRIDE + ((lane >> 4) * 16u);
    const u32 b_off = (u32)(warp_n + (lane & 7) + ((lane >> 4) & 1) * 8) * RSTRIDE +
                      ((lane >> 3) & 1) * 16u;

#pragma unroll
    for (int i = 0; i < 4; i++)
#pragma unroll
        for (int j = 0; j < 4; j++)
#pragma unroll
            for (int q = 0; q < 4; q++) A.a[i][j][q] = 0.0f;

    const int NCHUNK = K >> 6;  // 32 chunks of BK=64
    const f16* planes[2] = {Ah, Bh};

    // 2048 16B data chunks per stage (2 planes x 128 rows x 8), 256 thr -> 8 each
    auto issue_stage = [&](int s, int ki) {
        const int kofs = ki * 64;
#pragma unroll
        for (int i = 0; i < 8; i++) {
            const int c = i * 256 + tid;
            const int pl = c >> 10;
            const int cc = c & 1023;
            const int row = cc >> 3;
            const int ch = cc & 7;
            const size_t grow = (pl == 0 ? arow0 : brow0) + row;
            const f16* src = planes[pl] + grow * K + kofs + ch * 8;
            const u32 dst = sb + s * STAGE_B + pl * PLANE_B + row * RSTRIDE + ch * 16;
            CP_ASYNC16(dst, src);
        }
    };

    issue_stage(0, 0); CP_COMMIT();
    issue_stage(1, 1); CP_COMMIT();

    int sidx = 0;
    for (int ki = 0; ki < NCHUNK; ki++) {
        CP_WAIT(1);
        __syncthreads();
        const u32 stage = sb + (u32)sidx * STAGE_B;

#pragma unroll
        for (int ks = 0; ks < 4; ks++) {
            const u32 kbyte = (u32)ks * 32u;
            u32 ah[4][4], bh[4][2];
#pragma unroll
            for (int mt = 0; mt < 4; mt++)
                ldmx4(ah[mt], stage + a_off + (u32)mt * (16u * RSTRIDE) + kbyte);
#pragma unroll
            for (int np = 0; np < 2; np++) {
                u32 t[4];
                ldmx4(t, stage + PLANE_B + b_off + (u32)np * (16u * RSTRIDE) + kbyte);
                bh[2 * np][0] = t[0]; bh[2 * np][1] = t[1];
                bh[2 * np + 1][0] = t[2]; bh[2 * np + 1][1] = t[3];
            }
#pragma unroll
            for (int mt = 0; mt < 4; mt++)
#pragma unroll
                for (int nt = 0; nt < 4; nt++)
                    mma16816(A.a[mt][nt], ah[mt], bh[nt]);
        }
        if (ki + 2 < NCHUNK) {
            int ns = sidx + 2; if (ns >= NSTAGE) ns -= NSTAGE;
            issue_stage(ns, ki + 2);
        }
        CP_COMMIT();
        if (++sidx >= NSTAGE) sidx = 0;
    }
}

// ---------------- fused QKV GEMM, single-pass fp16 (gridDim.z = 3) ----------------
__global__ void __launch_bounds__(256, 2)
gemm_qkv(const f16* __restrict__ Xhi,
         const f16* __restrict__ WQh, const f16* __restrict__ WKh,
         const f16* __restrict__ WVh,
         f16* __restrict__ Qh, f16* __restrict__ Ql,
         f16* __restrict__ Kh, f16* __restrict__ Vh) {
    const int z = blockIdx.z;
    const f16* Bh;
    f16 *Chi, *Clo;
    if (z == 0)      { Bh = WQh; Chi = Qh; Clo = Ql; }
    else if (z == 1) { Bh = WKh; Chi = Kh; Clo = nullptr; }
    else             { Bh = WVh; Chi = Vh; Clo = nullptr; }
    const bool rope = (z < 2);

    AccT A;
    gemm_mainloop(Xhi, Bh,
                  (size_t)blockIdx.y * 128, (size_t)blockIdx.x * 128, D_MODEL, A);

    const int tid  = threadIdx.x;
    const int wid  = tid >> 5;
    const int lane = tid & 31;
    const int warp_m = (wid >> 2) * 64;
    const int warp_n = (wid & 3) * 32;
    const int rbase = blockIdx.y * 128 + warp_m + (lane >> 2);
    const int cbase = blockIdx.x * 128 + warp_n + (lane & 3) * 2;
#pragma unroll
    for (int mt = 0; mt < 4; mt++) {
#pragma unroll
        for (int half = 0; half < 2; half++) {
            const int grow = rbase + mt * 16 + half * 8;
            const int t = grow & (TLEN - 1);
#pragma unroll
            for (int nt = 0; nt < 4; nt++) {
                const int gcol = cbase + nt * 8;
                float e = A.a[mt][nt][half * 2 + 0];
                float o = A.a[mt][nt][half * 2 + 1];
                if (rope) {
                    const int kidx = (gcol & 127) >> 1;
                    const float cs = g_cos[t * 64 + kidx];
                    const float sn = g_sin[t * 64 + kidx];
                    const float e2 = e * cs - o * sn;
                    o = e * sn + o * cs;
                    e = e2;
                }
                const size_t idx = ((size_t)grow * D_MODEL + gcol) >> 1;
                if (Clo) {
                    u32 hi, lo;
                    split2h(e, o, hi, lo);
                    ((u32*)Chi)[idx] = hi;
                    ((u32*)Clo)[idx] = lo;
                } else {
                    ((u32*)Chi)[idx] = pack1h(e, o);
                }
            }
        }
    }
}

// ---------------- output GEMM, single-pass (fp32 out) ----------------
__global__ void __launch_bounds__(256, 2)
gemm_out(const f16* __restrict__ Ah, const f16* __restrict__ Bh,
         float* __restrict__ Cf) {
    AccT A;
    gemm_mainloop(Ah, Bh,
                  (size_t)blockIdx.y * 128, (size_t)blockIdx.x * 128, D_MODEL, A);

    const int tid  = threadIdx.x;
    const int wid  = tid >> 5;
    const int lane = tid & 31;
    const int warp_m = (wid >> 2) * 64;
    const int warp_n = (wid & 3) * 32;
    const int rbase = blockIdx.y * 128 + warp_m + (lane >> 2);
    const int cbase = blockIdx.x * 128 + warp_n + (lane & 3) * 2;
#pragma unroll
    for (int mt = 0; mt < 4; mt++)
#pragma unroll
        for (int half = 0; half < 2; half++) {
            const int grow = rbase + mt * 16 + half * 8;
#pragma unroll
            for (int nt = 0; nt < 4; nt++) {
                const int gcol = cbase + nt * 8;
                float2 v;
                v.x = A.a[mt][nt][half * 2 + 0];
                v.y = A.a[mt][nt][half * 2 + 1];
                *(float2*)(Cf + (size_t)grow * D_MODEL + gcol) = v;
            }
        }
}

// ---------------- attention: one CTA per (b,h), staged K/V waits ----------------
#define AT_PLANE  (128 * 272)
#define ATT_SMEM  (2 * AT_PLANE)       // Kh + Vh

__global__ void __launch_bounds__(256, 1)
attn_mma(const f16* __restrict__ Qhi, const f16* __restrict__ Qlo,
         const f16* __restrict__ Khi, const f16* __restrict__ Vhi,
         f16* __restrict__ Ahi) {
    extern __shared__ char smem[];
    const u32 sb = smem_u32(smem);
    const u32 skh = sb;
    const u32 svh = sb + AT_PLANE;

    const int bh_ = blockIdx.x;
    const int b = bh_ >> 4;
    const int h = bh_ & 15;
    const int tid = threadIdx.x;
    const int w = tid >> 5;
    const int l = tid & 31;

    // K plane first (own commit group), then V plane
    {
#pragma unroll
        for (int i = 0; i < 8; i++) {
            const int c = i * 256 + tid;
            const int row = c >> 4;
            const int ch = c & 15;
            const f16* src = Khi + ((size_t)(b * 128 + row)) * D_MODEL + h * 128 + ch * 8;
            CP_ASYNC16(skh + row * 272 + ch * 16, src);
        }
        CP_COMMIT();
#pragma unroll
        for (int i = 0; i < 8; i++) {
            const int c = i * 256 + tid;
            const int row = c >> 4;
            const int ch = c & 15;
            const f16* src = Vhi + ((size_t)(b * 128 + row)) * D_MODEL + h * 128 + ch * 8;
            CP_ASYNC16(svh + row * 272 + ch * 16, src);
        }
        CP_COMMIT();
    }

    u32 aQh[8][4], aQl[8][4];
    {
        const u32* qh32 = (const u32*)Qhi;
        const u32* ql32 = (const u32*)Qlo;
        const size_t r0 = (size_t)(b * 128 + 16 * w + (l >> 2)) * (D_MODEL / 2) + h * 64 + (l & 3);
        const size_t r8 = r0 + 8 * (D_MODEL / 2);
#pragma unroll
        for (int kt = 0; kt < 8; kt++) {
            const size_t o = (size_t)kt * 8;
            aQh[kt][0] = qh32[r0 + o];     aQh[kt][1] = qh32[r8 + o];
            aQh[kt][2] = qh32[r0 + o + 4]; aQh[kt][3] = qh32[r8 + o + 4];
            aQl[kt][0] = ql32[r0 + o];     aQl[kt][1] = ql32[r8 + o];
            aQl[kt][2] = ql32[r0 + o + 4]; aQl[kt][3] = ql32[r8 + o + 4];
        }
    }
    CP_WAIT(1);          // K resident; V still in flight
    __syncthreads();

    float S[16][4];
#pragma unroll
    for (int nt = 0; nt < 16; nt++)
#pragma unroll
        for (int q = 0; q < 4; q++) S[nt][q] = 0.0f;

    const u32 kb_off = (u32)((l & 7) + 8 * ((l >> 4) & 1)) * 272u + ((l >> 3) & 1) * 16u;
#pragma unroll
    for (int np = 0; np < 8; np++) {
        if (np <= w) {
#pragma unroll
            for (int kt = 0; kt < 8; kt++) {
                u32 kh[4];
                const u32 ro = (u32)np * (16u * 272u) + (u32)kt * 32u;
                ldmx4(kh, skh + kb_off + ro);
                u32 bh0[2] = {kh[0], kh[1]}, bh1[2] = {kh[2], kh[3]};
                mma16816(S[2 * np],     aQh[kt], bh0);
                mma16816(S[2 * np + 1], aQh[kt], bh1);
                mma16816(S[2 * np],     aQl[kt], bh0);
                mma16816(S[2 * np + 1], aQl[kt], bh1);
            }
        }
    }

    const int q0 = 16 * w + (l >> 2);
    const int q1 = q0 + 8;
    const float scale = 0.08838834764831845f;
    float m0 = -1.0e30f, m1 = -1.0e30f;
#pragma unroll
    for (int nt = 0; nt < 16; nt++) {
        if (nt <= 2 * w + 1) {
            const int kc = nt * 8 + 2 * (l & 3);
            if (kc > q0)     S[nt][0] = -1.0e30f;
            if (kc + 1 > q0) S[nt][1] = -1.0e30f;
            if (kc > q1)     S[nt][2] = -1.0e30f;
            if (kc + 1 > q1) S[nt][3] = -1.0e30f;
            m0 = fmaxf(m0, fmaxf(S[nt][0], S[nt][1]));
            m1 = fmaxf(m1, fmaxf(S[nt][2], S[nt][3]));
        }
    }
    m0 = fmaxf(m0, __shfl_xor_sync(0xffffffffu, m0, 1));
    m0 = fmaxf(m0, __shfl_xor_sync(0xffffffffu, m0, 2));
    m1 = fmaxf(m1, __shfl_xor_sync(0xffffffffu, m1, 1));
    m1 = fmaxf(m1, __shfl_xor_sync(0xffffffffu, m1, 2));

    float sum0 = 0.0f, sum1 = 0.0f;
#pragma unroll
    for (int nt = 0; nt < 16; nt++) {
        if (nt <= 2 * w + 1) {
            S[nt][0] = __expf((S[nt][0] - m0) * scale);
            S[nt][1] = __expf((S[nt][1] - m0) * scale);
            S[nt][2] = __expf((S[nt][2] - m1) * scale);
            S[nt][3] = __expf((S[nt][3] - m1) * scale);
            sum0 += S[nt][0] + S[nt][1];
            sum1 += S[nt][2] + S[nt][3];
        }
    }
    sum0 += __shfl_xor_sync(0xffffffffu, sum0, 1);
    sum0 += __shfl_xor_sync(0xffffffffu, sum0, 2);
    sum1 += __shfl_xor_sync(0xffffffffu, sum1, 1);
    sum1 += __shfl_xor_sync(0xffffffffu, sum1, 2);
    const float inv0 = 1.0f / sum0;
    const float inv1 = 1.0f / sum1;

    u32 ph[8][4], pl[8][4];
#pragma unroll
    for (int j = 0; j < 8; j++) {
        if (j <= w) {
            split2h(S[2 * j][0],     S[2 * j][1],     ph[j][0], pl[j][0]);
            split2h(S[2 * j][2],     S[2 * j][3],     ph[j][1], pl[j][1]);
            split2h(S[2 * j + 1][0], S[2 * j + 1][1], ph[j][2], pl[j][2]);
            split2h(S[2 * j + 1][2], S[2 * j + 1][3], ph[j][3], pl[j][3]);
        }
    }

    CP_WAIT(0);          // V resident
    __syncthreads();

    float O[16][4];
#pragma unroll
    for (int nt = 0; nt < 16; nt++)
#pragma unroll
        for (int q = 0; q < 4; q++) O[nt][q] = 0.0f;

    const u32 vb_row = (u32)((l & 7) + 8 * ((l >> 3) & 1)) * 272u + ((l >> 4) & 1) * 16u;
#pragma unroll
    for (int j = 0; j < 8; j++) {
        if (j <= w) {
#pragma unroll
            for (int dp = 0; dp < 8; dp += 2) {
                u32 vh0[4], vh1[4];
                const u32 ro0 = (u32)j * (16u * 272u) + (u32)dp * 32u;
                const u32 ro1 = ro0 + 32u;
                ldmx4t(vh0, svh + vb_row + ro0);
                ldmx4t(vh1, svh + vb_row + ro1);
                u32 h00[2] = {vh0[0], vh0[1]}, h01[2] = {vh0[2], vh0[3]};
                u32 h10[2] = {vh1[0], vh1[1]}, h11[2] = {vh1[2], vh1[3]};
                float* O0 = O[2 * dp];
                float* O1 = O[2 * dp + 1];
                float* O2 = O[2 * dp + 2];
                float* O3 = O[2 * dp + 3];
                mma16816(O0, ph[j], h00); mma16816(O1, ph[j], h01);
                mma16816(O2, ph[j], h10); mma16816(O3, ph[j], h11);
                mma16816(O0, pl[j], h00); mma16816(O1, pl[j], h01);
                mma16816(O2, pl[j], h10); mma16816(O3, pl[j], h11);
            }
        }
    }

    {
        u32* ah32 = (u32*)Ahi;
        const size_t rA = (size_t)(b * 128 + q0) * (D_MODEL / 2) + h * 64 + (l & 3);
        const size_t rB = rA + 8 * (D_MODEL / 2);
#pragma unroll
        for (int nt = 0; nt < 16; nt++) {
            ah32[rA + nt * 4] = pack1h(O[nt][0] * inv0, O[nt][1] * inv0);
            ah32[rB + nt * 4] = pack1h(O[nt][2] * inv1, O[nt][3] * inv1);
        }
    }
}

// ---------------- launch ----------------
extern "C" void kernel_launch(void* const* d_in, const int* in_sizes, int n_in,
                              void* d_out, int out_size) {
    const float* x  = (const float*)d_in[0];
    const float* WQ = (const float*)d_in[1];
    const float* WK = (const float*)d_in[2];
    const float* WV = (const float*)d_in[3];
    const float* WO = (const float*)d_in[4];
    float* out = (float*)d_out;

    static f16 *xhi, *qhi, *qlo, *khi, *vhi, *ahi;
    static f16 *wqh, *wkh, *wvh, *woh;
    static bool inited = false;
    if (!inited) {
        cudaGetSymbolAddress((void**)&xhi, g_xhi);
        cudaGetSymbolAddress((void**)&qhi, g_qhi); cudaGetSymbolAddress((void**)&qlo, g_qlo);
        cudaGetSymbolAddress((void**)&khi, g_khi); cudaGetSymbolAddress((void**)&vhi, g_vhi);
        cudaGetSymbolAddress((void**)&ahi, g_ahi);
        cudaGetSymbolAddress((void**)&wqh, g_wqh); cudaGetSymbolAddress((void**)&wkh, g_wkh);
        cudaGetSymbolAddress((void**)&wvh, g_wvh); cudaGetSymbolAddress((void**)&woh, g_woh);
        cudaFuncSetAttribute(gemm_qkv, cudaFuncAttributeMaxDynamicSharedMemorySize, GEMM_SMEM_1);
        cudaFuncSetAttribute(gemm_out, cudaFuncAttributeMaxDynamicSharedMemorySize, GEMM_SMEM_1);
        cudaFuncSetAttribute(attn_mma, cudaFuncAttributeMaxDynamicSharedMemorySize, ATT_SMEM);
        inited = true;
    }

    const int ntot = NX4 + 4 * NW4;
    split_all<<<(ntot + 255) / 256, 256>>>(x, WQ, WK, WV, WO,
                                           xhi, wqh, wkh, wvh, woh);

    dim3 gq(D_MODEL / 128, NROWS / 128, 3);   // (16, 64, 3)
    dim3 blk(256);
    gemm_qkv<<<gq, blk, GEMM_SMEM_1>>>(xhi, wqh, wkh, wvh, qhi, qlo, khi, vhi);

    attn_mma<<<BATCH * NHEADS, 256, ATT_SMEM>>>(qhi, qlo, khi, vhi, ahi);

    dim3 go(D_MODEL / 128, NROWS / 128);      // (16, 64)
    gemm_out<<<go, blk, GEMM_SMEM_1>>>(ahi, woh, out);
}